// round 8
// baseline (speedup 1.0000x reference)
#include <cuda_runtime.h>
#include <math.h>

// ---------------------------------------------------------------------------
// Problem constants (fixed shapes from reference)
// ---------------------------------------------------------------------------
#define T_TOK   4096          // B*S tokens
#define D_IN    1024          // d_model
#define H_DIM   4096          // hidden
#define E_EXP   8             // experts
#define R_RANK  32            // LoRA rank
#define SCALING 0.03125f      // 1/R
#define MAX_TILES 40          // sum ceil(c_e/128) <= 32 + 8 (worst case 39)

// ---------------------------------------------------------------------------
// Device scratch (static globals: allocation-free per harness rules)
// ---------------------------------------------------------------------------
__device__ int   g_idx[T_TOK];                       // top-1 expert per token
__device__ int   g_perm[T_TOK];                      // tokens sorted by expert
__device__ int   g_tile_expert[MAX_TILES];
__device__ int   g_tile_start[MAX_TILES];            // start index into g_perm
__device__ int   g_tile_rows[MAX_TILES];             // rows in tile (0 = unused)
__device__ float g_h[T_TOK * R_RANK];                // rank-stage activations
__device__ float g_abuf[(size_t)T_TOK * H_DIM];      // gelu(down) activations
__device__ float g_lora[(size_t)T_TOK * H_DIM];      // lora + bias staging buffer

// ---------------------------------------------------------------------------
// Kernel 1: router — logits, softmax, argmax, write routing + expert_choice
// ---------------------------------------------------------------------------
__global__ void router_kernel(const float* __restrict__ x,
                              const float* __restrict__ rw,
                              const float* __restrict__ rb,
                              float* __restrict__ routing,
                              float* __restrict__ ec)
{
    const int t = blockIdx.x;
    __shared__ float xs[D_IN];
    __shared__ float lg[E_EXP];
    const int tid = threadIdx.x;            // 256 threads

    ((float4*)xs)[tid] = ((const float4*)(x + (size_t)t * D_IN))[tid];
    __syncthreads();

    const int w = tid >> 5, lane = tid & 31;   // 8 warps = 8 experts
    const float* wrow = rw + (size_t)w * D_IN;
    float s = 0.f;
    for (int d = lane; d < D_IN; d += 32) s += xs[d] * wrow[d];
#pragma unroll
    for (int o = 16; o; o >>= 1) s += __shfl_xor_sync(0xFFFFFFFFu, s, o);
    if (lane == 0) lg[w] = s + rb[w];
    __syncthreads();

    if (tid == 0) {
        float m = lg[0]; int am = 0;
#pragma unroll
        for (int e = 1; e < E_EXP; e++) if (lg[e] > m) { m = lg[e]; am = e; }
        float ex[E_EXP]; float den = 0.f;
#pragma unroll
        for (int e = 0; e < E_EXP; e++) { ex[e] = expf(lg[e] - m); den += ex[e]; }
        const float inv = 1.f / den;
#pragma unroll
        for (int e = 0; e < E_EXP; e++) {
            const float r = ex[e] * inv;
            routing[t * E_EXP + e] = r;
            const float msk = (e == am) ? 1.f : 0.f;
            ec[t * E_EXP + e] = (msk - r) + r;   // matches ref fp order
        }
        g_idx[t] = am;
    }
}

// ---------------------------------------------------------------------------
// Kernel 2: group tokens by expert, build perm + tile map (single block)
// ---------------------------------------------------------------------------
__global__ void group_kernel()
{
    __shared__ int cnt[E_EXP];
    __shared__ int base[E_EXP];
    const int tid = threadIdx.x;   // 256
    if (tid < E_EXP) cnt[tid] = 0;
    __syncthreads();
    for (int t = tid; t < T_TOK; t += 256) atomicAdd(&cnt[g_idx[t]], 1);
    __syncthreads();
    if (tid == 0) {
        int off = 0, slot = 0;
        for (int e = 0; e < E_EXP; e++) {
            base[e] = off;
            const int c = cnt[e];
            for (int s = 0; s < c; s += 128) {
                g_tile_expert[slot] = e;
                g_tile_start[slot]  = off + s;
                g_tile_rows[slot]   = min(128, c - s);
                slot++;
            }
            off += c;
        }
        for (; slot < MAX_TILES; slot++) g_tile_rows[slot] = 0;
    }
    __syncthreads();
    if (tid < E_EXP) cnt[tid] = base[tid];   // reuse as cursors
    __syncthreads();
    for (int t = tid; t < T_TOK; t += 256) {
        const int e = g_idx[t];
        const int pos = atomicAdd(&cnt[e], 1);
        g_perm[pos] = t;
    }
}

// ---------------------------------------------------------------------------
// Kernel 3: zero the rank-stage buffer (k-split accumulation via atomics)
// ---------------------------------------------------------------------------
__global__ void zero_h_kernel()
{
    const int i = blockIdx.x * blockDim.x + threadIdx.x;
    if (i < T_TOK * R_RANK) g_h[i] = 0.f;
}

// ---------------------------------------------------------------------------
// Kernel 4: grouped rank stage  h[t,r] += dot(in[t, k0:k0+kchunk], A[e,r,...])
// grid: (MAX_TILES, K/kchunk), 256 threads. BM=128 tokens x 32 ranks per tile.
// ---------------------------------------------------------------------------
__global__ void rank_kernel(const float* __restrict__ in, int K, int kchunk,
                            const float* __restrict__ A,     // [E][R][K]
                            const float* __restrict__ Ab)    // [E][R]
{
    const int slot = blockIdx.x;
    const int rows = g_tile_rows[slot];
    if (rows == 0) return;
    const int e     = g_tile_expert[slot];
    const int start = g_tile_start[slot];
    const int k0    = blockIdx.y * kchunk;

    __shared__ float xs[32][132];   // [k][token]
    __shared__ float as_s[32][36];  // [k][r]
    __shared__ int   perm_s[128];

    const int tid = threadIdx.x;
    if (tid < 128) perm_s[tid] = (tid < rows) ? g_perm[start + tid] : 0;
    const int tg = tid >> 3;   // token group (0..31), 4 tokens each
    const int rg = tid & 7;    // rank group  (0..7),  4 ranks each
    float acc[4][4];
#pragma unroll
    for (int i = 0; i < 4; i++)
#pragma unroll
        for (int j = 0; j < 4; j++) acc[i][j] = 0.f;
    __syncthreads();

    for (int kk = k0; kk < k0 + kchunk; kk += 32) {
        __syncthreads();   // protect previous-iteration smem reads
        // x tile: 128 rows x 32 cols = 1024 float4; 4 per thread
#pragma unroll
        for (int q = 0; q < 4; q++) {
            const int f = q * 256 + tid;
            const int i = f >> 3, c = (f & 7) * 4;
            float4 v = make_float4(0.f, 0.f, 0.f, 0.f);
            if (i < rows) v = *(const float4*)(in + (size_t)perm_s[i] * K + kk + c);
            xs[c + 0][i] = v.x; xs[c + 1][i] = v.y;
            xs[c + 2][i] = v.z; xs[c + 3][i] = v.w;
        }
        // A tile: 32 r x 32 k = 256 float4; 1 per thread
        {
            const int r = tid >> 3, c = (tid & 7) * 4;
            const float4 v = *(const float4*)(A + ((size_t)e * R_RANK + r) * K + kk + c);
            as_s[c + 0][r] = v.x; as_s[c + 1][r] = v.y;
            as_s[c + 2][r] = v.z; as_s[c + 3][r] = v.w;
        }
        __syncthreads();
#pragma unroll
        for (int k = 0; k < 32; k++) {
            float a_[4], b_[4];
#pragma unroll
            for (int i = 0; i < 4; i++) a_[i] = xs[k][tg * 4 + i];
#pragma unroll
            for (int j = 0; j < 4; j++) b_[j] = as_s[k][rg * 4 + j];
#pragma unroll
            for (int i = 0; i < 4; i++)
#pragma unroll
                for (int j = 0; j < 4; j++) acc[i][j] += a_[i] * b_[j];
        }
    }

#pragma unroll
    for (int i = 0; i < 4; i++) {
        const int irow = tg * 4 + i;
        if (irow < rows) {
            const int t = perm_s[irow];
#pragma unroll
            for (int j = 0; j < 4; j++) {
                const int r = rg * 4 + j;
                float v = acc[i][j];
                if (blockIdx.y == 0) v += Ab[e * R_RANK + r];
                atomicAdd(&g_h[t * R_RANK + r], v);
            }
        }
    }
}

// ---------------------------------------------------------------------------
// Kernel 5: grouped LoRA B-stage + biases:
//   outb[t,n] = SCALING * (h[t,:] . Bw[e,n,:] + Bb[e,n]) + bias[n]
// grid: (MAX_TILES, N/128), 256 threads. BM=128 tokens x BN=128 cols, K=32.
// ---------------------------------------------------------------------------
__global__ __launch_bounds__(256)
void lorab_kernel(const float* __restrict__ Bw,   // [E][N][R]
                  const float* __restrict__ Bb,   // [E][N]
                  const float* __restrict__ bias, // [N]
                  int N, float* __restrict__ outb)
{
    const int slot = blockIdx.x;
    const int rows = g_tile_rows[slot];
    if (rows == 0) return;
    const int e     = g_tile_expert[slot];
    const int start = g_tile_start[slot];
    const int bn    = blockIdx.y * 128;

    __shared__ float hs[32][132];   // [r][token]
    __shared__ float bs[32][132];   // [r][n]
    __shared__ int   perm_s[128];

    const int tid = threadIdx.x;
    if (tid < 128) perm_s[tid] = (tid < rows) ? g_perm[start + tid] : 0;
    __syncthreads();

#pragma unroll
    for (int q = 0; q < 4; q++) {      // h tile: 128 x 32
        const int f = q * 256 + tid;
        const int i = f >> 3, c = (f & 7) * 4;
        float4 v = make_float4(0.f, 0.f, 0.f, 0.f);
        if (i < rows) v = *(const float4*)(g_h + perm_s[i] * R_RANK + c);
        hs[c + 0][i] = v.x; hs[c + 1][i] = v.y;
        hs[c + 2][i] = v.z; hs[c + 3][i] = v.w;
    }
#pragma unroll
    for (int q = 0; q < 4; q++) {      // B tile: 128 x 32
        const int f = q * 256 + tid;
        const int n = f >> 3, c = (f & 7) * 4;
        const float4 v = *(const float4*)(Bw + ((size_t)e * N + bn + n) * R_RANK + c);
        bs[c + 0][n] = v.x; bs[c + 1][n] = v.y;
        bs[c + 2][n] = v.z; bs[c + 3][n] = v.w;
    }
    __syncthreads();

    const int tx = tid & 15, ty = tid >> 4;
    float acc[8][8];
#pragma unroll
    for (int i = 0; i < 8; i++)
#pragma unroll
        for (int j = 0; j < 8; j++) acc[i][j] = 0.f;

#pragma unroll
    for (int k = 0; k < 32; k++) {
        const float4 af0 = *(const float4*)&hs[k][ty * 8];
        const float4 af1 = *(const float4*)&hs[k][ty * 8 + 4];
        const float4 bf0 = *(const float4*)&bs[k][tx * 8];
        const float4 bf1 = *(const float4*)&bs[k][tx * 8 + 4];
        const float a_[8] = {af0.x, af0.y, af0.z, af0.w, af1.x, af1.y, af1.z, af1.w};
        const float b_[8] = {bf0.x, bf0.y, bf0.z, bf0.w, bf1.x, bf1.y, bf1.z, bf1.w};
#pragma unroll
        for (int i = 0; i < 8; i++)
#pragma unroll
            for (int j = 0; j < 8; j++) acc[i][j] += a_[i] * b_[j];
    }

#pragma unroll
    for (int i = 0; i < 8; i++) {
        const int irow = ty * 8 + i;
        if (irow < rows) {
            const int t  = perm_s[irow];
            const int n0 = bn + tx * 8;
#pragma unroll
            for (int j = 0; j < 8; j++) {
                const int n = n0 + j;
                outb[(size_t)t * N + n] =
                    SCALING * (acc[i][j] + Bb[(size_t)e * N + n]) + bias[n];
            }
        }
    }
}

// ---------------------------------------------------------------------------
// Kernel 6: main dense GEMM (TN):  C[m,n] = sum_k A[m,k]*B[n,k] + addbuf[m,n]
// optional exact GELU. BM=BN=128, BK=16, 256 threads, 8x8 per thread.
// grid: (N/128, M/128)
// ---------------------------------------------------------------------------
__global__ __launch_bounds__(256, 2)
void gemm_kernel(const float* __restrict__ A, const float* __restrict__ B,
                 const float* __restrict__ addbuf, float* __restrict__ C,
                 int N, int K, int do_gelu)
{
    __shared__ float As[16][132];
    __shared__ float Bs[16][132];

    const int tid = threadIdx.x;
    const int bm = blockIdx.y * 128;
    const int bn = blockIdx.x * 128;
    const int tx = tid & 15;
    const int ty = tid >> 4;

    // loader mapping: 512 float4 per tile, 2 per thread (rows r and r+64)
    const int rowL = tid >> 2;              // 0..63
    const int colL = (tid & 3) * 4;         // 0,4,8,12

    const float* aP0 = A + (size_t)(bm + rowL)      * K + colL;
    const float* aP1 = A + (size_t)(bm + rowL + 64) * K + colL;
    const float* bP0 = B + (size_t)(bn + rowL)      * K + colL;
    const float* bP1 = B + (size_t)(bn + rowL + 64) * K + colL;

    float acc[8][8];
#pragma unroll
    for (int i = 0; i < 8; i++)
#pragma unroll
        for (int j = 0; j < 8; j++) acc[i][j] = 0.f;

    for (int kk = 0; kk < K; kk += 16) {
        const float4 a0 = *(const float4*)aP0;
        const float4 a1 = *(const float4*)aP1;
        const float4 b0 = *(const float4*)bP0;
        const float4 b1 = *(const float4*)bP1;
        aP0 += 16; aP1 += 16; bP0 += 16; bP1 += 16;

        __syncthreads();   // previous-iteration readers done
        As[colL + 0][rowL] = a0.x; As[colL + 1][rowL] = a0.y;
        As[colL + 2][rowL] = a0.z; As[colL + 3][rowL] = a0.w;
        As[colL + 0][rowL + 64] = a1.x; As[colL + 1][rowL + 64] = a1.y;
        As[colL + 2][rowL + 64] = a1.z; As[colL + 3][rowL + 64] = a1.w;
        Bs[colL + 0][rowL] = b0.x; Bs[colL + 1][rowL] = b0.y;
        Bs[colL + 2][rowL] = b0.z; Bs[colL + 3][rowL] = b0.w;
        Bs[colL + 0][rowL + 64] = b1.x; Bs[colL + 1][rowL + 64] = b1.y;
        Bs[colL + 2][rowL + 64] = b1.z; Bs[colL + 3][rowL + 64] = b1.w;
        __syncthreads();

#pragma unroll
        for (int k = 0; k < 16; k++) {
            const float4 af0 = *(const float4*)&As[k][ty * 8];
            const float4 af1 = *(const float4*)&As[k][ty * 8 + 4];
            const float4 bf0 = *(const float4*)&Bs[k][tx * 8];
            const float4 bf1 = *(const float4*)&Bs[k][tx * 8 + 4];
            const float a_[8] = {af0.x, af0.y, af0.z, af0.w, af1.x, af1.y, af1.z, af1.w};
            const float b_[8] = {bf0.x, bf0.y, bf0.z, bf0.w, bf1.x, bf1.y, bf1.z, bf1.w};
#pragma unroll
            for (int i = 0; i < 8; i++)
#pragma unroll
                for (int j = 0; j < 8; j++) acc[i][j] += a_[i] * b_[j];
        }
    }

    // epilogue: add lora/bias buffer, optional exact GELU, store
#pragma unroll
    for (int i = 0; i < 8; i++) {
        const int m = bm + ty * 8 + i;
        const float* addp = addbuf + (size_t)m * N + bn + tx * 8;
        float*       outp = C      + (size_t)m * N + bn + tx * 8;
#pragma unroll
        for (int j = 0; j < 8; j++) {
            float v = acc[i][j] + addp[j];
            if (do_gelu) v = 0.5f * v * (1.f + erff(v * 0.70710678118654752f));
            outp[j] = v;
        }
    }
}

// ---------------------------------------------------------------------------
// Launch sequence (graph-capturable: kernel launches on default stream only)
// ---------------------------------------------------------------------------
extern "C" void kernel_launch(void* const* d_in, const int* in_sizes, int n_in,
                              void* d_out, int out_size)
{
    (void)in_sizes; (void)n_in; (void)out_size;
    const float* x     = (const float*)d_in[0];
    const float* rw    = (const float*)d_in[1];
    const float* rb    = (const float*)d_in[2];
    const float* fc1w  = (const float*)d_in[3];
    const float* fc1b  = (const float*)d_in[4];
    const float* fc2w  = (const float*)d_in[5];
    const float* fc2b  = (const float*)d_in[6];
    const float* A_dn  = (const float*)d_in[7];
    const float* Ab_dn = (const float*)d_in[8];
    const float* B_dn  = (const float*)d_in[9];
    const float* Bb_dn = (const float*)d_in[10];
    const float* A_up  = (const float*)d_in[11];
    const float* Ab_up = (const float*)d_in[12];
    const float* B_up  = (const float*)d_in[13];
    const float* Bb_up = (const float*)d_in[14];

    float* out    = (float*)d_out;
    float* out_up = out;                                   // [T, D]
    float* out_rt = out + (size_t)T_TOK * D_IN;            // [T, E]
    float* out_ec = out_rt + (size_t)T_TOK * E_EXP;        // [T, E]

    float *abuf_p = nullptr, *lora_p = nullptr;
    cudaGetSymbolAddress((void**)&abuf_p, g_abuf);
    cudaGetSymbolAddress((void**)&lora_p, g_lora);

    // 1. router: routing, expert_choice, idx
    router_kernel<<<T_TOK, 256>>>(x, rw, rb, out_rt, out_ec);
    // 2. sort tokens by expert, build tile map
    group_kernel<<<1, 256>>>();

    // ---- down projection: fc1 + LoRA_down, exact GELU ----
    zero_h_kernel<<<(T_TOK * R_RANK + 255) / 256, 256>>>();
    rank_kernel<<<dim3(MAX_TILES, D_IN / 256), 256>>>(x, D_IN, 256, A_dn, Ab_dn);
    lorab_kernel<<<dim3(MAX_TILES, H_DIM / 128), 256>>>(B_dn, Bb_dn, fc1b, H_DIM, lora_p);
    gemm_kernel<<<dim3(H_DIM / 128, T_TOK / 128), 256>>>(x, fc1w, lora_p, abuf_p,
                                                         H_DIM, D_IN, 1);

    // ---- up projection: fc2 + LoRA_up ----
    zero_h_kernel<<<(T_TOK * R_RANK + 255) / 256, 256>>>();
    rank_kernel<<<dim3(MAX_TILES, H_DIM / 512), 256>>>(abuf_p, H_DIM, 512, A_up, Ab_up);
    lorab_kernel<<<dim3(MAX_TILES, D_IN / 128), 256>>>(B_up, Bb_up, fc2b, D_IN, lora_p);
    gemm_kernel<<<dim3(D_IN / 128, T_TOK / 128), 256>>>(abuf_p, fc2w, lora_p, out_up,
                                                        D_IN, H_DIM, 0);
}

// round 9
// speedup vs baseline: 1.0028x; 1.0028x over previous
#include <cuda_runtime.h>
#include <math.h>

// ---------------------------------------------------------------------------
// Problem constants (fixed shapes from reference)
// ---------------------------------------------------------------------------
#define T_TOK   4096          // B*S tokens
#define D_IN    1024          // d_model
#define H_DIM   4096          // hidden
#define E_EXP   8             // experts
#define R_RANK  32            // LoRA rank
#define SCALING 0.03125f      // 1/R
#define MAX_TILES 40          // sum ceil(c_e/128) <= 32 + 8 (worst case 39)

// ---------------------------------------------------------------------------
// Device scratch (static globals: allocation-free per harness rules)
// ---------------------------------------------------------------------------
__device__ int   g_idx[T_TOK];                       // top-1 expert per token
__device__ int   g_perm[T_TOK];                      // tokens sorted by expert
__device__ int   g_tile_expert[MAX_TILES];
__device__ int   g_tile_start[MAX_TILES];            // start index into g_perm
__device__ int   g_tile_rows[MAX_TILES];             // rows in tile (0 = unused)
__device__ float g_h[T_TOK * R_RANK];                // rank-stage activations
__device__ float g_abuf[(size_t)T_TOK * H_DIM];      // gelu(down) activations
__device__ float g_lora[(size_t)T_TOK * H_DIM];      // lora + bias staging buffer

// ---------------------------------------------------------------------------
// Kernel 1: router — logits, softmax, argmax, write routing + expert_choice
// ---------------------------------------------------------------------------
__global__ void router_kernel(const float* __restrict__ x,
                              const float* __restrict__ rw,
                              const float* __restrict__ rb,
                              float* __restrict__ routing,
                              float* __restrict__ ec)
{
    const int t = blockIdx.x;
    __shared__ float xs[D_IN];
    __shared__ float lg[E_EXP];
    const int tid = threadIdx.x;            // 256 threads

    ((float4*)xs)[tid] = ((const float4*)(x + (size_t)t * D_IN))[tid];
    __syncthreads();

    const int w = tid >> 5, lane = tid & 31;   // 8 warps = 8 experts
    const float* wrow = rw + (size_t)w * D_IN;
    float s = 0.f;
    for (int d = lane; d < D_IN; d += 32) s += xs[d] * wrow[d];
#pragma unroll
    for (int o = 16; o; o >>= 1) s += __shfl_xor_sync(0xFFFFFFFFu, s, o);
    if (lane == 0) lg[w] = s + rb[w];
    __syncthreads();

    if (tid == 0) {
        float m = lg[0]; int am = 0;
#pragma unroll
        for (int e = 1; e < E_EXP; e++) if (lg[e] > m) { m = lg[e]; am = e; }
        float ex[E_EXP]; float den = 0.f;
#pragma unroll
        for (int e = 0; e < E_EXP; e++) { ex[e] = expf(lg[e] - m); den += ex[e]; }
        const float inv = 1.f / den;
#pragma unroll
        for (int e = 0; e < E_EXP; e++) {
            const float r = ex[e] * inv;
            routing[t * E_EXP + e] = r;
            const float msk = (e == am) ? 1.f : 0.f;
            ec[t * E_EXP + e] = (msk - r) + r;   // matches ref fp order
        }
        g_idx[t] = am;
    }
}

// ---------------------------------------------------------------------------
// Kernel 2: group tokens by expert, build perm + tile map (single block)
// ---------------------------------------------------------------------------
__global__ void group_kernel()
{
    __shared__ int cnt[E_EXP];
    __shared__ int base[E_EXP];
    const int tid = threadIdx.x;   // 256
    if (tid < E_EXP) cnt[tid] = 0;
    __syncthreads();
    for (int t = tid; t < T_TOK; t += 256) atomicAdd(&cnt[g_idx[t]], 1);
    __syncthreads();
    if (tid == 0) {
        int off = 0, slot = 0;
        for (int e = 0; e < E_EXP; e++) {
            base[e] = off;
            const int c = cnt[e];
            for (int s = 0; s < c; s += 128) {
                g_tile_expert[slot] = e;
                g_tile_start[slot]  = off + s;
                g_tile_rows[slot]   = min(128, c - s);
                slot++;
            }
            off += c;
        }
        for (; slot < MAX_TILES; slot++) g_tile_rows[slot] = 0;
    }
    __syncthreads();
    if (tid < E_EXP) cnt[tid] = base[tid];   // reuse as cursors
    __syncthreads();
    for (int t = tid; t < T_TOK; t += 256) {
        const int e = g_idx[t];
        const int pos = atomicAdd(&cnt[e], 1);
        g_perm[pos] = t;
    }
}

// ---------------------------------------------------------------------------
// Kernel 3: zero the rank-stage buffer (k-split accumulation via atomics)
// ---------------------------------------------------------------------------
__global__ void zero_h_kernel()
{
    const int i = blockIdx.x * blockDim.x + threadIdx.x;
    if (i < T_TOK * R_RANK) g_h[i] = 0.f;
}

// ---------------------------------------------------------------------------
// Kernel 4: grouped rank stage  h[t,r] += dot(in[t, k0:k0+kchunk], A[e,r,...])
// grid: (MAX_TILES, K/kchunk), 256 threads. BM=128 tokens x 32 ranks per tile.
// ---------------------------------------------------------------------------
__global__ void rank_kernel(const float* __restrict__ in, int K, int kchunk,
                            const float* __restrict__ A,     // [E][R][K]
                            const float* __restrict__ Ab)    // [E][R]
{
    const int slot = blockIdx.x;
    const int rows = g_tile_rows[slot];
    if (rows == 0) return;
    const int e     = g_tile_expert[slot];
    const int start = g_tile_start[slot];
    const int k0    = blockIdx.y * kchunk;

    __shared__ float xs[32][132];   // [k][token]
    __shared__ float as_s[32][36];  // [k][r]
    __shared__ int   perm_s[128];

    const int tid = threadIdx.x;
    if (tid < 128) perm_s[tid] = (tid < rows) ? g_perm[start + tid] : 0;
    const int tg = tid >> 3;   // token group (0..31), 4 tokens each
    const int rg = tid & 7;    // rank group  (0..7),  4 ranks each
    float acc[4][4];
#pragma unroll
    for (int i = 0; i < 4; i++)
#pragma unroll
        for (int j = 0; j < 4; j++) acc[i][j] = 0.f;
    __syncthreads();

    for (int kk = k0; kk < k0 + kchunk; kk += 32) {
        __syncthreads();   // protect previous-iteration smem reads
        // x tile: 128 rows x 32 cols = 1024 float4; 4 per thread
#pragma unroll
        for (int q = 0; q < 4; q++) {
            const int f = q * 256 + tid;
            const int i = f >> 3, c = (f & 7) * 4;
            float4 v = make_float4(0.f, 0.f, 0.f, 0.f);
            if (i < rows) v = *(const float4*)(in + (size_t)perm_s[i] * K + kk + c);
            xs[c + 0][i] = v.x; xs[c + 1][i] = v.y;
            xs[c + 2][i] = v.z; xs[c + 3][i] = v.w;
        }
        // A tile: 32 r x 32 k = 256 float4; 1 per thread
        {
            const int r = tid >> 3, c = (tid & 7) * 4;
            const float4 v = *(const float4*)(A + ((size_t)e * R_RANK + r) * K + kk + c);
            as_s[c + 0][r] = v.x; as_s[c + 1][r] = v.y;
            as_s[c + 2][r] = v.z; as_s[c + 3][r] = v.w;
        }
        __syncthreads();
#pragma unroll
        for (int k = 0; k < 32; k++) {
            float a_[4], b_[4];
#pragma unroll
            for (int i = 0; i < 4; i++) a_[i] = xs[k][tg * 4 + i];
#pragma unroll
            for (int j = 0; j < 4; j++) b_[j] = as_s[k][rg * 4 + j];
#pragma unroll
            for (int i = 0; i < 4; i++)
#pragma unroll
                for (int j = 0; j < 4; j++) acc[i][j] += a_[i] * b_[j];
        }
    }

#pragma unroll
    for (int i = 0; i < 4; i++) {
        const int irow = tg * 4 + i;
        if (irow < rows) {
            const int t = perm_s[irow];
#pragma unroll
            for (int j = 0; j < 4; j++) {
                const int r = rg * 4 + j;
                float v = acc[i][j];
                if (blockIdx.y == 0) v += Ab[e * R_RANK + r];
                atomicAdd(&g_h[t * R_RANK + r], v);
            }
        }
    }
}

// ---------------------------------------------------------------------------
// Kernel 5: grouped LoRA B-stage + biases:
//   outb[t,n] = SCALING * (h[t,:] . Bw[e,n,:] + Bb[e,n]) + bias[n]
// grid: (MAX_TILES, N/128), 256 threads. BM=128 tokens x BN=128 cols, K=32.
// ---------------------------------------------------------------------------
__global__ __launch_bounds__(256)
void lorab_kernel(const float* __restrict__ Bw,   // [E][N][R]
                  const float* __restrict__ Bb,   // [E][N]
                  const float* __restrict__ bias, // [N]
                  int N, float* __restrict__ outb)
{
    const int slot = blockIdx.x;
    const int rows = g_tile_rows[slot];
    if (rows == 0) return;
    const int e     = g_tile_expert[slot];
    const int start = g_tile_start[slot];
    const int bn    = blockIdx.y * 128;

    __shared__ float hs[32][132];   // [r][token]
    __shared__ float bs[32][132];   // [r][n]
    __shared__ int   perm_s[128];

    const int tid = threadIdx.x;
    if (tid < 128) perm_s[tid] = (tid < rows) ? g_perm[start + tid] : 0;
    __syncthreads();

#pragma unroll
    for (int q = 0; q < 4; q++) {      // h tile: 128 x 32
        const int f = q * 256 + tid;
        const int i = f >> 3, c = (f & 7) * 4;
        float4 v = make_float4(0.f, 0.f, 0.f, 0.f);
        if (i < rows) v = *(const float4*)(g_h + perm_s[i] * R_RANK + c);
        hs[c + 0][i] = v.x; hs[c + 1][i] = v.y;
        hs[c + 2][i] = v.z; hs[c + 3][i] = v.w;
    }
#pragma unroll
    for (int q = 0; q < 4; q++) {      // B tile: 128 x 32
        const int f = q * 256 + tid;
        const int n = f >> 3, c = (f & 7) * 4;
        const float4 v = *(const float4*)(Bw + ((size_t)e * N + bn + n) * R_RANK + c);
        bs[c + 0][n] = v.x; bs[c + 1][n] = v.y;
        bs[c + 2][n] = v.z; bs[c + 3][n] = v.w;
    }
    __syncthreads();

    const int tx = tid & 15, ty = tid >> 4;
    float acc[8][8];
#pragma unroll
    for (int i = 0; i < 8; i++)
#pragma unroll
        for (int j = 0; j < 8; j++) acc[i][j] = 0.f;

#pragma unroll
    for (int k = 0; k < 32; k++) {
        const float4 af0 = *(const float4*)&hs[k][ty * 8];
        const float4 af1 = *(const float4*)&hs[k][ty * 8 + 4];
        const float4 bf0 = *(const float4*)&bs[k][tx * 8];
        const float4 bf1 = *(const float4*)&bs[k][tx * 8 + 4];
        const float a_[8] = {af0.x, af0.y, af0.z, af0.w, af1.x, af1.y, af1.z, af1.w};
        const float b_[8] = {bf0.x, bf0.y, bf0.z, bf0.w, bf1.x, bf1.y, bf1.z, bf1.w};
#pragma unroll
        for (int i = 0; i < 8; i++)
#pragma unroll
            for (int j = 0; j < 8; j++) acc[i][j] += a_[i] * b_[j];
    }

#pragma unroll
    for (int i = 0; i < 8; i++) {
        const int irow = ty * 8 + i;
        if (irow < rows) {
            const int t  = perm_s[irow];
            const int n0 = bn + tx * 8;
#pragma unroll
            for (int j = 0; j < 8; j++) {
                const int n = n0 + j;
                outb[(size_t)t * N + n] =
                    SCALING * (acc[i][j] + Bb[(size_t)e * N + n]) + bias[n];
            }
        }
    }
}

// ---------------------------------------------------------------------------
// Kernel 6: main dense GEMM (TN):  C[m,n] = sum_k A[m,k]*B[n,k] + addbuf[m,n]
// optional exact GELU. BM=BN=128, BK=16, 256 threads, 8x8 per thread.
// grid: (N/128, M/128)
// ---------------------------------------------------------------------------
__global__ __launch_bounds__(256, 2)
void gemm_kernel(const float* __restrict__ A, const float* __restrict__ B,
                 const float* __restrict__ addbuf, float* __restrict__ C,
                 int N, int K, int do_gelu)
{
    __shared__ float As[16][132];
    __shared__ float Bs[16][132];

    const int tid = threadIdx.x;
    const int bm = blockIdx.y * 128;
    const int bn = blockIdx.x * 128;
    const int tx = tid & 15;
    const int ty = tid >> 4;

    // loader mapping: 512 float4 per tile, 2 per thread (rows r and r+64)
    const int rowL = tid >> 2;              // 0..63
    const int colL = (tid & 3) * 4;         // 0,4,8,12

    const float* aP0 = A + (size_t)(bm + rowL)      * K + colL;
    const float* aP1 = A + (size_t)(bm + rowL + 64) * K + colL;
    const float* bP0 = B + (size_t)(bn + rowL)      * K + colL;
    const float* bP1 = B + (size_t)(bn + rowL + 64) * K + colL;

    float acc[8][8];
#pragma unroll
    for (int i = 0; i < 8; i++)
#pragma unroll
        for (int j = 0; j < 8; j++) acc[i][j] = 0.f;

    for (int kk = 0; kk < K; kk += 16) {
        const float4 a0 = *(const float4*)aP0;
        const float4 a1 = *(const float4*)aP1;
        const float4 b0 = *(const float4*)bP0;
        const float4 b1 = *(const float4*)bP1;
        aP0 += 16; aP1 += 16; bP0 += 16; bP1 += 16;

        __syncthreads();   // previous-iteration readers done
        As[colL + 0][rowL] = a0.x; As[colL + 1][rowL] = a0.y;
        As[colL + 2][rowL] = a0.z; As[colL + 3][rowL] = a0.w;
        As[colL + 0][rowL + 64] = a1.x; As[colL + 1][rowL + 64] = a1.y;
        As[colL + 2][rowL + 64] = a1.z; As[colL + 3][rowL + 64] = a1.w;
        Bs[colL + 0][rowL] = b0.x; Bs[colL + 1][rowL] = b0.y;
        Bs[colL + 2][rowL] = b0.z; Bs[colL + 3][rowL] = b0.w;
        Bs[colL + 0][rowL + 64] = b1.x; Bs[colL + 1][rowL + 64] = b1.y;
        Bs[colL + 2][rowL + 64] = b1.z; Bs[colL + 3][rowL + 64] = b1.w;
        __syncthreads();

#pragma unroll
        for (int k = 0; k < 16; k++) {
            const float4 af0 = *(const float4*)&As[k][ty * 8];
            const float4 af1 = *(const float4*)&As[k][ty * 8 + 4];
            const float4 bf0 = *(const float4*)&Bs[k][tx * 8];
            const float4 bf1 = *(const float4*)&Bs[k][tx * 8 + 4];
            const float a_[8] = {af0.x, af0.y, af0.z, af0.w, af1.x, af1.y, af1.z, af1.w};
            const float b_[8] = {bf0.x, bf0.y, bf0.z, bf0.w, bf1.x, bf1.y, bf1.z, bf1.w};
#pragma unroll
            for (int i = 0; i < 8; i++)
#pragma unroll
                for (int j = 0; j < 8; j++) acc[i][j] += a_[i] * b_[j];
        }
    }

    // epilogue: add lora/bias buffer, optional exact GELU, store
#pragma unroll
    for (int i = 0; i < 8; i++) {
        const int m = bm + ty * 8 + i;
        const float* addp = addbuf + (size_t)m * N + bn + tx * 8;
        float*       outp = C      + (size_t)m * N + bn + tx * 8;
#pragma unroll
        for (int j = 0; j < 8; j++) {
            float v = acc[i][j] + addp[j];
            if (do_gelu) v = 0.5f * v * (1.f + erff(v * 0.70710678118654752f));
            outp[j] = v;
        }
    }
}

// ---------------------------------------------------------------------------
// Launch sequence (graph-capturable: kernel launches on default stream only)
// ---------------------------------------------------------------------------
extern "C" void kernel_launch(void* const* d_in, const int* in_sizes, int n_in,
                              void* d_out, int out_size)
{
    (void)in_sizes; (void)n_in; (void)out_size;
    const float* x     = (const float*)d_in[0];
    const float* rw    = (const float*)d_in[1];
    const float* rb    = (const float*)d_in[2];
    const float* fc1w  = (const float*)d_in[3];
    const float* fc1b  = (const float*)d_in[4];
    const float* fc2w  = (const float*)d_in[5];
    const float* fc2b  = (const float*)d_in[6];
    const float* A_dn  = (const float*)d_in[7];
    const float* Ab_dn = (const float*)d_in[8];
    const float* B_dn  = (const float*)d_in[9];
    const float* Bb_dn = (const float*)d_in[10];
    const float* A_up  = (const float*)d_in[11];
    const float* Ab_up = (const float*)d_in[12];
    const float* B_up  = (const float*)d_in[13];
    const float* Bb_up = (const float*)d_in[14];

    float* out    = (float*)d_out;
    float* out_up = out;                                   // [T, D]
    float* out_rt = out + (size_t)T_TOK * D_IN;            // [T, E]
    float* out_ec = out_rt + (size_t)T_TOK * E_EXP;        // [T, E]

    float *abuf_p = nullptr, *lora_p = nullptr;
    cudaGetSymbolAddress((void**)&abuf_p, g_abuf);
    cudaGetSymbolAddress((void**)&lora_p, g_lora);

    // 1. router: routing, expert_choice, idx
    router_kernel<<<T_TOK, 256>>>(x, rw, rb, out_rt, out_ec);
    // 2. sort tokens by expert, build tile map
    group_kernel<<<1, 256>>>();

    // ---- down projection: fc1 + LoRA_down, exact GELU ----
    zero_h_kernel<<<(T_TOK * R_RANK + 255) / 256, 256>>>();
    rank_kernel<<<dim3(MAX_TILES, D_IN / 256), 256>>>(x, D_IN, 256, A_dn, Ab_dn);
    lorab_kernel<<<dim3(MAX_TILES, H_DIM / 128), 256>>>(B_dn, Bb_dn, fc1b, H_DIM, lora_p);
    gemm_kernel<<<dim3(H_DIM / 128, T_TOK / 128), 256>>>(x, fc1w, lora_p, abuf_p,
                                                         H_DIM, D_IN, 1);

    // ---- up projection: fc2 + LoRA_up ----
    zero_h_kernel<<<(T_TOK * R_RANK + 255) / 256, 256>>>();
    rank_kernel<<<dim3(MAX_TILES, H_DIM / 512), 256>>>(abuf_p, H_DIM, 512, A_up, Ab_up);
    lorab_kernel<<<dim3(MAX_TILES, D_IN / 128), 256>>>(B_up, Bb_up, fc2b, D_IN, lora_p);
    gemm_kernel<<<dim3(D_IN / 128, T_TOK / 128), 256>>>(abuf_p, fc2w, lora_p, out_up,
                                                        D_IN, H_DIM, 0);
}